// round 6
// baseline (speedup 1.0000x reference)
#include <cuda_runtime.h>

#define HH    136
#define WWW   200
#define HW    (HH*WWW)
#define OH    272
#define OW    400
#define NIMG  8
#define NINST 512
#define NPAR  169
#define TB    128

typedef unsigned long long u64;

__device__ float g_part[NINST * 8 * 3];     // per-(inst,band) partials

__constant__ float c_soi[6] = {64.f, 128.f, 256.f, 512.f, 1024.f, 2048.f};

// ---------- packed f32x2 helpers ----------
__device__ __forceinline__ u64 pk(float lo, float hi) {
    u64 r; asm("mov.b64 %0, {%1,%2};" : "=l"(r) : "f"(lo), "f"(hi)); return r;
}
__device__ __forceinline__ u64 fma2(u64 a, u64 b, u64 c) {
    u64 d; asm("fma.rn.f32x2 %0, %1, %2, %3;" : "=l"(d) : "l"(a), "l"(b), "l"(c)); return d;
}
union F2 { u64 u; float f[2]; };
__device__ __forceinline__ u64 relu2(u64 v) {
    F2 x; x.u = v;
    x.f[0] = fmaxf(x.f[0], 0.f);
    x.f[1] = fmaxf(x.f[1], 0.f);
    return x.u;
}

// ---------- fused MLP + upsample + sigmoid + dice partials ----------
__global__ void __launch_bounds__(TB) mask_kernel(
    const float* __restrict__ mf,
    const float* __restrict__ params,
    const float* __restrict__ iloc,
    const float* __restrict__ gt,
    const int*   __restrict__ im_inds,
    const int*   __restrict__ fpn)
{
    const int b   = blockIdx.x;   // band 0..7 (17 input rows each)
    const int n   = blockIdx.y;   // instance
    const int tid = threadIdx.x;

    __shared__ __align__(16) float sw2[2 * NPAR];  // duplicated weights (LDS.64 packs)
    __shared__ __align__(16) u64   srx[WWW / 2];   // packed relx per pixel-pair
    __shared__ __align__(16) u64   sry[18];        // packed rely per band row
    __shared__ float sl[18 * WWW];                 // band logits
    __shared__ int   tx0[OW];
    __shared__ float twx[OW];
    __shared__ float red[3][TB / 32];

    const int   im   = __ldg(&im_inds[n]);
    const float sinv = 1.f / c_soi[__ldg(&fpn[n])];
    const float locx = __ldg(&iloc[2 * n]);
    const float locy = __ldg(&iloc[2 * n + 1]);

    const int r0    = b * 17;
    const int nrows = min(18, HH - r0);            // 18, last band 17

    for (int i = tid; i < NPAR; i += TB) {
        float v = params[n * NPAR + i];
        sw2[2 * i] = v; sw2[2 * i + 1] = v;
    }
    for (int xp = tid; xp < WWW / 2; xp += TB) {
        int x = 2 * xp;
        srx[xp] = pk((locx - (float)(8 * x + 4))  * sinv,
                     (locx - (float)(8 * x + 12)) * sinv);
    }
    for (int r = tid; r < nrows; r += TB) {
        float ry = (locy - (float)(8 * (r0 + r) + 4)) * sinv;
        sry[r] = pk(ry, ry);
    }
    for (int j = tid; j < OW; j += TB) {
        float fx = (float)j * (199.f / 399.f);
        int x0 = (int)fx;
        tx0[j] = x0;
        twx[j] = fx - (float)x0;
    }
    __syncthreads();

#define WLD(i) (*(const u64*)(sw2 + 2 * (i)))

    const int nchunks = nrows * 25;                // 8-px chunks per band
    const float* fimg = mf + (size_t)im * 8 * HW;

    // ---- phase 1: logits (8 px = 4 f32x2 packs per chunk) ----
    for (int g = tid; g < nchunks; g += TB) {
        const int row = g / 25;
        const int cx  = g - row * 25;
        const int xb  = cx * 8;
        const float* fb = fimg + (r0 + row) * WWW + xb;

        // front-batched feat loads: 16 independent LDG.128
        ulonglong2 fA[8], fB[8];
#pragma unroll
        for (int c = 0; c < 8; c++) {
            fA[c] = *(const ulonglong2*)(fb + (size_t)c * HW);
            fB[c] = *(const ulonglong2*)(fb + (size_t)c * HW + 4);
        }
        u64 xr0 = srx[cx * 4], xr1 = srx[cx * 4 + 1];
        u64 xr2 = srx[cx * 4 + 2], xr3 = srx[cx * 4 + 3];
        u64 yrl = sry[row];

        // layer 1
        u64 acc[8][4];
#pragma unroll
        for (int o = 0; o < 8; o++) {
            u64 bb = WLD(152 + o);
            u64 w0 = WLD(o * 10);
            u64 w1 = WLD(o * 10 + 1);
            acc[o][0] = fma2(w1, yrl, fma2(w0, xr0, bb));
            acc[o][1] = fma2(w1, yrl, fma2(w0, xr1, bb));
            acc[o][2] = fma2(w1, yrl, fma2(w0, xr2, bb));
            acc[o][3] = fma2(w1, yrl, fma2(w0, xr3, bb));
        }
#pragma unroll
        for (int c = 0; c < 8; c++) {
#pragma unroll
            for (int o = 0; o < 8; o++) {
                u64 w = WLD(o * 10 + 2 + c);
                acc[o][0] = fma2(w, fA[c].x, acc[o][0]);
                acc[o][1] = fma2(w, fA[c].y, acc[o][1]);
                acc[o][2] = fma2(w, fB[c].x, acc[o][2]);
                acc[o][3] = fma2(w, fB[c].y, acc[o][3]);
            }
        }
        u64 h[8][4];
#pragma unroll
        for (int o = 0; o < 8; o++)
#pragma unroll
            for (int p = 0; p < 4; p++) h[o][p] = relu2(acc[o][p]);

        // layer 2
        u64 a2[8][4];
#pragma unroll
        for (int o = 0; o < 8; o++) {
            u64 bb = WLD(160 + o);
            a2[o][0] = bb; a2[o][1] = bb; a2[o][2] = bb; a2[o][3] = bb;
        }
#pragma unroll
        for (int c = 0; c < 8; c++) {
#pragma unroll
            for (int o = 0; o < 8; o++) {
                u64 w = WLD(80 + o * 8 + c);
                a2[o][0] = fma2(w, h[c][0], a2[o][0]);
                a2[o][1] = fma2(w, h[c][1], a2[o][1]);
                a2[o][2] = fma2(w, h[c][2], a2[o][2]);
                a2[o][3] = fma2(w, h[c][3], a2[o][3]);
            }
        }
        u64 h2[8][4];
#pragma unroll
        for (int o = 0; o < 8; o++)
#pragma unroll
            for (int p = 0; p < 4; p++) h2[o][p] = relu2(a2[o][p]);

        // layer 3
        u64 ov[4];
        {
            u64 bb = WLD(168);
            ov[0] = bb; ov[1] = bb; ov[2] = bb; ov[3] = bb;
        }
#pragma unroll
        for (int c = 0; c < 8; c++) {
            u64 w = WLD(144 + c);
            ov[0] = fma2(w, h2[c][0], ov[0]);
            ov[1] = fma2(w, h2[c][1], ov[1]);
            ov[2] = fma2(w, h2[c][2], ov[2]);
            ov[3] = fma2(w, h2[c][3], ov[3]);
        }
        u64* slp = (u64*)&sl[row * WWW + xb];      // 8B-aligned (xb even)
        slp[0] = ov[0]; slp[1] = ov[1]; slp[2] = ov[2]; slp[3] = ov[3];
    }
    __syncthreads();

    // ---- phase 2: upsample + sigmoid + dice partials ----
    const int i_start = (r0 * 271 + 134) / 135;
    const int i_end   = (b == 7) ? OH : ((r0 + 17) * 271 + 134) / 135;
    const float* gtb  = gt + (size_t)n * OH * OW;

    float aI = 0.f, aS = 0.f, aT = 0.f;
    for (int i = i_start; i < i_end; i++) {
        const float fy = (float)i * (135.f / 271.f);
        const int   y0 = (int)fy;
        const float wy = fy - (float)y0;
        int ly0 = y0 - r0;
        int ly1 = min(y0 + 1, 135) - r0;
        ly0 = max(0, min(ly0, nrows - 1));
        ly1 = max(0, min(ly1, nrows - 1));
        const float* sl0 = &sl[ly0 * WWW];
        const float* sl1 = &sl[ly1 * WWW];
        const float* gtr = gtb + (size_t)i * OW;

        for (int j = tid; j < OW; j += TB) {
            int   x0 = tx0[j];
            float wx = twx[j];
            int   x1 = min(x0 + 1, 199);

            float t00 = sl0[x0], t01 = sl0[x1];
            float t10 = sl1[x0], t11 = sl1[x1];
            float top = t00 + (t01 - t00) * wx;
            float bot = t10 + (t11 - t10) * wx;
            float v   = top + (bot - top) * wy;

            float s = __fdividef(1.f, 1.f + __expf(-v));
            float t = __ldg(&gtr[j]);

            aI = fmaf(s, t, aI);
            aS = fmaf(s, s, aS);
            aT += t;                               // t ∈ {0,1}
        }
    }

#pragma unroll
    for (int off = 16; off > 0; off >>= 1) {
        aI += __shfl_down_sync(0xffffffffu, aI, off);
        aS += __shfl_down_sync(0xffffffffu, aS, off);
        aT += __shfl_down_sync(0xffffffffu, aT, off);
    }
    const int wid = tid >> 5, lane = tid & 31;
    if (lane == 0) { red[0][wid] = aI; red[1][wid] = aS; red[2][wid] = aT; }
    __syncthreads();
    if (tid == 0) {
        float I = 0.f, S = 0.f, T = 0.f;
#pragma unroll
        for (int w = 0; w < TB / 32; w++) { I += red[0][w]; S += red[1][w]; T += red[2][w]; }
        float* gp = &g_part[(n * 8 + b) * 3];
        gp[0] = I; gp[1] = S; gp[2] = T;
    }
}

// ---------- finalize dice loss ----------
__global__ void finalize_kernel(float* __restrict__ out) {
    int n = blockIdx.x * blockDim.x + threadIdx.x;
    if (n >= NINST) return;
    float I = 0.f, S = 0.f, T = 0.f;
#pragma unroll
    for (int b = 0; b < 8; b++) {
        const float* gp = &g_part[(n * 8 + b) * 3];
        I += gp[0]; S += gp[1]; T += gp[2];
    }
    out[n] = 1.f - 2.f * I / (S + T + 1e-5f);
}

// no-op: pads the per-call launch sequence to 5 so ncu's "skip 5, capture 1"
// lands on mask_kernel (launch idx 5 = first launch of the second call).
__global__ void dummy_kernel() {}

extern "C" void kernel_launch(void* const* d_in, const int* in_sizes, int n_in,
                              void* d_out, int out_size) {
    const float* mf     = (const float*)d_in[0];
    const float* params = (const float*)d_in[1];
    const float* iloc   = (const float*)d_in[2];
    const float* gt     = (const float*)d_in[3];
    const int*   imi    = (const int*)d_in[4];
    const int*   fpn    = (const int*)d_in[5];
    float*       out    = (float*)d_out;

    dim3 grid(8, NINST);
    mask_kernel<<<grid, TB>>>(mf, params, iloc, gt, imi, fpn);
    finalize_kernel<<<1, NINST>>>(out);
    dummy_kernel<<<1, 1>>>();
    dummy_kernel<<<1, 1>>>();
    dummy_kernel<<<1, 1>>>();
}

// round 7
// speedup vs baseline: 1.0322x; 1.0322x over previous
#include <cuda_runtime.h>

#define HH    136
#define WWW   200
#define HW    (HH*WWW)
#define OH    272
#define OW    400
#define NIMG  8
#define NINST 512
#define NPAR  169
#define TB    128

typedef unsigned long long u64;

__device__ float g_part[NINST * 8 * 3];   // per-(inst,band) partials
__device__ int   g_count[NINST];          // zero-init; finisher resets -> graph-safe

__constant__ float c_soi[6] = {64.f, 128.f, 256.f, 512.f, 1024.f, 2048.f};

// ---------- packed f32x2 helpers ----------
__device__ __forceinline__ u64 pk(float lo, float hi) {
    u64 r; asm("mov.b64 %0, {%1,%2};" : "=l"(r) : "f"(lo), "f"(hi)); return r;
}
__device__ __forceinline__ u64 fma2(u64 a, u64 b, u64 c) {
    u64 d; asm("fma.rn.f32x2 %0, %1, %2, %3;" : "=l"(d) : "l"(a), "l"(b), "l"(c)); return d;
}
union F2 { u64 u; float f[2]; };
__device__ __forceinline__ u64 relu2(u64 v) {
    F2 x; x.u = v;
    x.f[0] = fmaxf(x.f[0], 0.f);
    x.f[1] = fmaxf(x.f[1], 0.f);
    return x.u;
}

// ---------- single fused kernel: MLP + upsample + sigmoid + dice + finalize ----------
__global__ void __launch_bounds__(TB) mask_kernel(
    const float* __restrict__ mf,
    const float* __restrict__ params,
    const float* __restrict__ iloc,
    const float* __restrict__ gt,
    const int*   __restrict__ im_inds,
    const int*   __restrict__ fpn,
    float*       __restrict__ out)
{
    const int b   = blockIdx.x;   // band 0..7 (17 input rows each)
    const int n   = blockIdx.y;   // instance
    const int tid = threadIdx.x;

    __shared__ __align__(16) float sw2[2 * NPAR];  // duplicated weights -> LDS.64 packs
    __shared__ __align__(16) u64   srx[WWW / 2];   // packed relx per pixel-pair
    __shared__ __align__(16) u64   sry[18];        // packed rely per band row
    __shared__ float sl[18 * WWW];                 // band logits
    __shared__ float red[3][TB / 32];

    const int   im   = __ldg(&im_inds[n]);
    const float sinv = 1.f / c_soi[__ldg(&fpn[n])];
    const float locx = __ldg(&iloc[2 * n]);
    const float locy = __ldg(&iloc[2 * n + 1]);

    const int r0    = b * 17;
    const int nrows = min(18, HH - r0);            // 18, last band 17

    for (int i = tid; i < NPAR; i += TB) {
        float v = params[n * NPAR + i];
        sw2[2 * i] = v; sw2[2 * i + 1] = v;
    }
    for (int xp = tid; xp < WWW / 2; xp += TB) {
        int x = 2 * xp;
        srx[xp] = pk((locx - (float)(8 * x + 4))  * sinv,
                     (locx - (float)(8 * x + 12)) * sinv);
    }
    for (int r = tid; r < nrows; r += TB) {
        float ry = (locy - (float)(8 * (r0 + r) + 4)) * sinv;
        sry[r] = pk(ry, ry);
    }
    __syncthreads();

#define WLD(i) (*(const u64*)(sw2 + 2 * (i)))

    const int nchunks = nrows * 25;                // 8-px chunks per band
    const float* fimg = mf + (size_t)im * 8 * HW;

    // ---- phase 1: logits (8 px = 4 f32x2 packs/chunk; feats interleaved -> low liveness) ----
    for (int g = tid; g < nchunks; g += TB) {
        const int row = g / 25;
        const int cx  = g - row * 25;
        const int xb  = cx * 8;
        const float* fb = fimg + (r0 + row) * WWW + xb;

        // layer 1: bias + rel-coord channels
        u64 acc[8][4];
        {
            u64 xr0 = srx[cx * 4],     xr1 = srx[cx * 4 + 1];
            u64 xr2 = srx[cx * 4 + 2], xr3 = srx[cx * 4 + 3];
            u64 yrl = sry[row];
#pragma unroll
            for (int o = 0; o < 8; o++) {
                u64 bb = WLD(152 + o);
                u64 w0 = WLD(o * 10);
                u64 w1 = WLD(o * 10 + 1);
                acc[o][0] = fma2(w1, yrl, fma2(w0, xr0, bb));
                acc[o][1] = fma2(w1, yrl, fma2(w0, xr1, bb));
                acc[o][2] = fma2(w1, yrl, fma2(w0, xr2, bb));
                acc[o][3] = fma2(w1, yrl, fma2(w0, xr3, bb));
            }
        }
        // feat channels, one at a time (keeps only 2 float4 live)
#pragma unroll
        for (int c = 0; c < 8; c++) {
            float4 vlo = *(const float4*)(fb + (size_t)c * HW);
            float4 vhi = *(const float4*)(fb + (size_t)c * HW + 4);
            u64 x0 = pk(vlo.x, vlo.y), x1 = pk(vlo.z, vlo.w);
            u64 x2 = pk(vhi.x, vhi.y), x3 = pk(vhi.z, vhi.w);
#pragma unroll
            for (int o = 0; o < 8; o++) {
                u64 w = WLD(o * 10 + 2 + c);
                acc[o][0] = fma2(w, x0, acc[o][0]);
                acc[o][1] = fma2(w, x1, acc[o][1]);
                acc[o][2] = fma2(w, x2, acc[o][2]);
                acc[o][3] = fma2(w, x3, acc[o][3]);
            }
        }
        u64 h[8][4];
#pragma unroll
        for (int o = 0; o < 8; o++)
#pragma unroll
            for (int p = 0; p < 4; p++) h[o][p] = relu2(acc[o][p]);

        // layer 2 (reuse acc storage)
#pragma unroll
        for (int o = 0; o < 8; o++) {
            u64 bb = WLD(160 + o);
            acc[o][0] = bb; acc[o][1] = bb; acc[o][2] = bb; acc[o][3] = bb;
        }
#pragma unroll
        for (int c = 0; c < 8; c++) {
#pragma unroll
            for (int o = 0; o < 8; o++) {
                u64 w = WLD(80 + o * 8 + c);
                acc[o][0] = fma2(w, h[c][0], acc[o][0]);
                acc[o][1] = fma2(w, h[c][1], acc[o][1]);
                acc[o][2] = fma2(w, h[c][2], acc[o][2]);
                acc[o][3] = fma2(w, h[c][3], acc[o][3]);
            }
        }
        // layer 3 accumulated directly (h2 never materialized as full array)
        u64 ov0 = WLD(168), ov1 = ov0, ov2 = ov0, ov3 = ov0;
#pragma unroll
        for (int c = 0; c < 8; c++) {
            u64 w = WLD(144 + c);
            ov0 = fma2(w, relu2(acc[c][0]), ov0);
            ov1 = fma2(w, relu2(acc[c][1]), ov1);
            ov2 = fma2(w, relu2(acc[c][2]), ov2);
            ov3 = fma2(w, relu2(acc[c][3]), ov3);
        }
        u64* slp = (u64*)&sl[row * WWW + xb];      // 8B-aligned (xb even)
        slp[0] = ov0; slp[1] = ov1; slp[2] = ov2; slp[3] = ov3;
    }
    __syncthreads();

    // ---- phase 2: upsample + sigmoid + dice partials ----
    const int i_start = (r0 * 271 + 134) / 135;
    const int i_end   = (b == 7) ? OH : ((r0 + 17) * 271 + 134) / 135;
    const float* gtb  = gt + (size_t)n * OH * OW;

    float aI = 0.f, aS = 0.f, aT = 0.f;
    for (int i = i_start; i < i_end; i++) {
        const float fy = (float)i * (135.f / 271.f);
        const int   y0 = (int)fy;
        const float wy = fy - (float)y0;
        int ly0 = y0 - r0;
        int ly1 = min(y0 + 1, 135) - r0;
        ly0 = max(0, min(ly0, nrows - 1));
        ly1 = max(0, min(ly1, nrows - 1));
        const float* sl0 = &sl[ly0 * WWW];
        const float* sl1 = &sl[ly1 * WWW];
        const float* gtr = gtb + (size_t)i * OW;

        for (int j = tid; j < OW; j += TB) {
            float fx = (float)j * (199.f / 399.f);
            int   x0 = (int)fx;
            float wx = fx - (float)x0;
            int   x1 = min(x0 + 1, 199);

            float t00 = sl0[x0], t01 = sl0[x1];
            float t10 = sl1[x0], t11 = sl1[x1];
            float top = t00 + (t01 - t00) * wx;
            float bot = t10 + (t11 - t10) * wx;
            float v   = top + (bot - top) * wy;

            float s = __fdividef(1.f, 1.f + __expf(-v));
            float t = __ldg(&gtr[j]);

            aI = fmaf(s, t, aI);
            aS = fmaf(s, s, aS);
            aT += t;                               // t in {0,1}
        }
    }

#pragma unroll
    for (int off = 16; off > 0; off >>= 1) {
        aI += __shfl_down_sync(0xffffffffu, aI, off);
        aS += __shfl_down_sync(0xffffffffu, aS, off);
        aT += __shfl_down_sync(0xffffffffu, aT, off);
    }
    const int wid = tid >> 5, lane = tid & 31;
    if (lane == 0) { red[0][wid] = aI; red[1][wid] = aS; red[2][wid] = aT; }
    __syncthreads();

    // ---- phase 3: last band-block per instance finalizes the loss ----
    if (tid == 0) {
        float I = red[0][0] + red[0][1] + red[0][2] + red[0][3];
        float S = red[1][0] + red[1][1] + red[1][2] + red[1][3];
        float T = red[2][0] + red[2][1] + red[2][2] + red[2][3];
        float* gp = &g_part[(n * 8 + b) * 3];
        gp[0] = I; gp[1] = S; gp[2] = T;
        __threadfence();
        int old = atomicAdd(&g_count[n], 1);
        if (old == 7) {                 // I'm the last band of this instance
            __threadfence();
            float sI = 0.f, sS = 0.f, sT = 0.f;
#pragma unroll
            for (int k = 0; k < 8; k++) {
                const float* q = &g_part[(n * 8 + k) * 3];
                sI += q[0]; sS += q[1]; sT += q[2];
            }
            out[n] = 1.f - 2.f * sI / (sS + sT + 1e-5f);
            g_count[n] = 0;             // reset for next graph replay
        }
    }
}

extern "C" void kernel_launch(void* const* d_in, const int* in_sizes, int n_in,
                              void* d_out, int out_size) {
    const float* mf     = (const float*)d_in[0];
    const float* params = (const float*)d_in[1];
    const float* iloc   = (const float*)d_in[2];
    const float* gt     = (const float*)d_in[3];
    const int*   imi    = (const int*)d_in[4];
    const int*   fpn    = (const int*)d_in[5];
    float*       out    = (float*)d_out;

    dim3 grid(8, NINST);
    mask_kernel<<<grid, TB>>>(mf, params, iloc, gt, imi, fpn, out);
}

// round 8
// speedup vs baseline: 1.1524x; 1.1164x over previous
#include <cuda_runtime.h>

#define HH    136
#define WWW   200
#define HW    (HH*WWW)
#define OH    272
#define OW    400
#define NIMG  8
#define NINST 512
#define NPAR  169
#define TB    128

typedef unsigned long long u64;

__device__ float g_part[NINST * 8 * 3];   // per-(inst,band) partials
__device__ int   g_count[NINST];          // zero-init; finisher resets -> graph-safe

__constant__ float c_soi[6] = {64.f, 128.f, 256.f, 512.f, 1024.f, 2048.f};

// ---------- packed f32x2 helpers ----------
__device__ __forceinline__ u64 pk(float lo, float hi) {
    u64 r; asm("mov.b64 %0, {%1,%2};" : "=l"(r) : "f"(lo), "f"(hi)); return r;
}
__device__ __forceinline__ u64 fma2(u64 a, u64 b, u64 c) {
    u64 d; asm("fma.rn.f32x2 %0, %1, %2, %3;" : "=l"(d) : "l"(a), "l"(b), "l"(c)); return d;
}
union F2 { u64 u; float f[2]; };
__device__ __forceinline__ u64 relu2(u64 v) {
    F2 x; x.u = v;
    x.f[0] = fmaxf(x.f[0], 0.f);
    x.f[1] = fmaxf(x.f[1], 0.f);
    return x.u;
}

// ---------- single fused kernel: MLP + upsample + sigmoid + dice + finalize ----------
// 2 pixels (one f32x2 pack) per thread per chunk -> minimal register liveness,
// high occupancy. Weights read from smem as broadcast LDS.64 (pre-duplicated).
__global__ void __launch_bounds__(TB) mask_kernel(
    const float* __restrict__ mf,
    const float* __restrict__ params,
    const float* __restrict__ iloc,
    const float* __restrict__ gt,
    const int*   __restrict__ im_inds,
    const int*   __restrict__ fpn,
    float*       __restrict__ out)
{
    const int b   = blockIdx.x;   // band 0..7 (17 input rows each)
    const int n   = blockIdx.y;   // instance
    const int tid = threadIdx.x;

    __shared__ __align__(16) float sw2[2 * NPAR];  // duplicated weights -> LDS.64 packs
    __shared__ __align__(16) u64   srx[WWW / 2];   // packed relx per pixel-pair
    __shared__ __align__(16) u64   sry[18];        // packed rely per band row
    __shared__ float sl[18 * WWW];                 // band logits
    __shared__ float red[3][TB / 32];

    const int   im   = __ldg(&im_inds[n]);
    const float sinv = 1.f / c_soi[__ldg(&fpn[n])];
    const float locx = __ldg(&iloc[2 * n]);
    const float locy = __ldg(&iloc[2 * n + 1]);

    const int r0    = b * 17;
    const int nrows = min(18, HH - r0);            // 18, last band 17

    for (int i = tid; i < NPAR; i += TB) {
        float v = params[n * NPAR + i];
        sw2[2 * i] = v; sw2[2 * i + 1] = v;
    }
    for (int xp = tid; xp < WWW / 2; xp += TB) {
        int x = 2 * xp;
        srx[xp] = pk((locx - (float)(8 * x + 4))  * sinv,
                     (locx - (float)(8 * x + 12)) * sinv);
    }
    for (int r = tid; r < nrows; r += TB) {
        float ry = (locy - (float)(8 * (r0 + r) + 4)) * sinv;
        sry[r] = pk(ry, ry);
    }
    __syncthreads();

#define WLD(i) (*(const u64*)(sw2 + 2 * (i)))

    const int nchunks = nrows * 100;               // 2-px chunks per band
    const float* fimg = mf + (size_t)im * 8 * HW;

    // ---- phase 1: logits, one f32x2 pack per thread-iteration ----
    for (int g = tid; g < nchunks; g += TB) {
        const int row = g / 100;
        const int cx  = g - row * 100;
        const int xb  = cx * 2;
        const float* fb = fimg + (r0 + row) * WWW + xb;

        // layer 1
        u64 acc[8];
        {
            u64 xr = srx[cx];
            u64 yr = sry[row];
#pragma unroll
            for (int o = 0; o < 8; o++)
                acc[o] = fma2(WLD(o * 10 + 1), yr,
                         fma2(WLD(o * 10),     xr, WLD(152 + o)));
        }
#pragma unroll
        for (int c = 0; c < 8; c++) {
            u64 x = *(const u64*)(fb + (size_t)c * HW);   // 8B-aligned (xb even)
#pragma unroll
            for (int o = 0; o < 8; o++)
                acc[o] = fma2(WLD(o * 10 + 2 + c), x, acc[o]);
        }
        u64 h[8];
#pragma unroll
        for (int o = 0; o < 8; o++) h[o] = relu2(acc[o]);

        // layer 2 (reuse acc)
#pragma unroll
        for (int o = 0; o < 8; o++) acc[o] = WLD(160 + o);
#pragma unroll
        for (int c = 0; c < 8; c++) {
#pragma unroll
            for (int o = 0; o < 8; o++)
                acc[o] = fma2(WLD(80 + o * 8 + c), h[c], acc[o]);
        }

        // layer 3
        u64 ov = WLD(168);
#pragma unroll
        for (int c = 0; c < 8; c++)
            ov = fma2(WLD(144 + c), relu2(acc[c]), ov);

        *(u64*)&sl[row * WWW + xb] = ov;               // 8B-aligned
    }
    __syncthreads();

    // ---- phase 2: upsample + sigmoid + dice partials ----
    const int i_start = (r0 * 271 + 134) / 135;
    const int i_end   = (b == 7) ? OH : ((r0 + 17) * 271 + 134) / 135;
    const float* gtb  = gt + (size_t)n * OH * OW;

    float aI = 0.f, aS = 0.f, aT = 0.f;
    for (int i = i_start; i < i_end; i++) {
        const float fy = (float)i * (135.f / 271.f);
        const int   y0 = (int)fy;
        const float wy = fy - (float)y0;
        int ly0 = y0 - r0;
        int ly1 = min(y0 + 1, 135) - r0;
        ly0 = max(0, min(ly0, nrows - 1));
        ly1 = max(0, min(ly1, nrows - 1));
        const float* sl0 = &sl[ly0 * WWW];
        const float* sl1 = &sl[ly1 * WWW];
        const float* gtr = gtb + (size_t)i * OW;

        for (int j = tid; j < OW; j += TB) {
            float fx = (float)j * (199.f / 399.f);
            int   x0 = (int)fx;
            float wx = fx - (float)x0;
            int   x1 = min(x0 + 1, 199);

            float t00 = sl0[x0], t01 = sl0[x1];
            float t10 = sl1[x0], t11 = sl1[x1];
            float top = t00 + (t01 - t00) * wx;
            float bot = t10 + (t11 - t10) * wx;
            float v   = top + (bot - top) * wy;

            float s = __fdividef(1.f, 1.f + __expf(-v));
            float t = __ldg(&gtr[j]);

            aI = fmaf(s, t, aI);
            aS = fmaf(s, s, aS);
            aT += t;                               // t in {0,1}
        }
    }

#pragma unroll
    for (int off = 16; off > 0; off >>= 1) {
        aI += __shfl_down_sync(0xffffffffu, aI, off);
        aS += __shfl_down_sync(0xffffffffu, aS, off);
        aT += __shfl_down_sync(0xffffffffu, aT, off);
    }
    const int wid = tid >> 5, lane = tid & 31;
    if (lane == 0) { red[0][wid] = aI; red[1][wid] = aS; red[2][wid] = aT; }
    __syncthreads();

    // ---- phase 3: last band-block per instance finalizes the loss ----
    if (tid == 0) {
        float I = red[0][0] + red[0][1] + red[0][2] + red[0][3];
        float S = red[1][0] + red[1][1] + red[1][2] + red[1][3];
        float T = red[2][0] + red[2][1] + red[2][2] + red[2][3];
        float* gp = &g_part[(n * 8 + b) * 3];
        gp[0] = I; gp[1] = S; gp[2] = T;
        __threadfence();
        int old = atomicAdd(&g_count[n], 1);
        if (old == 7) {                 // last band of this instance
            __threadfence();
            float sI = 0.f, sS = 0.f, sT = 0.f;
#pragma unroll
            for (int k = 0; k < 8; k++) {
                const float* q = &g_part[(n * 8 + k) * 3];
                sI += q[0]; sS += q[1]; sT += q[2];
            }
            out[n] = 1.f - 2.f * sI / (sS + sT + 1e-5f);
            g_count[n] = 0;             // reset for next graph replay
        }
    }
}

extern "C" void kernel_launch(void* const* d_in, const int* in_sizes, int n_in,
                              void* d_out, int out_size) {
    const float* mf     = (const float*)d_in[0];
    const float* params = (const float*)d_in[1];
    const float* iloc   = (const float*)d_in[2];
    const float* gt     = (const float*)d_in[3];
    const int*   imi    = (const int*)d_in[4];
    const int*   fpn    = (const int*)d_in[5];
    float*       out    = (float*)d_out;

    dim3 grid(8, NINST);
    mask_kernel<<<grid, TB>>>(mf, params, iloc, gt, imi, fpn, out);
}

// round 10
// speedup vs baseline: 3.1234x; 2.7104x over previous
#include <cuda_runtime.h>

#define HH    136
#define WWW   200
#define HW    (HH*WWW)
#define OH    272
#define OW    400
#define NIMG  8
#define NINST 512
#define NPAR  169
#define TB    128

typedef unsigned long long u64;

__device__ float g_part[NINST * 8 * 3];   // per-(inst,band) partials
__device__ int   g_count[NINST];          // zero-init; finisher resets -> graph-safe

__constant__ float c_soi[6] = {64.f, 128.f, 256.f, 512.f, 1024.f, 2048.f};

// ---------- packed f32x2 helpers ----------
__device__ __forceinline__ u64 pk(float lo, float hi) {
    u64 r; asm("mov.b64 %0, {%1,%2};" : "=l"(r) : "f"(lo), "f"(hi)); return r;
}
__device__ __forceinline__ u64 fma2(u64 a, u64 b, u64 c) {
    u64 d; asm("fma.rn.f32x2 %0, %1, %2, %3;" : "=l"(d) : "l"(a), "l"(b), "l"(c)); return d;
}
union F2 { u64 u; float f[2]; };
__device__ __forceinline__ u64 relu2(u64 v) {
    F2 x; x.u = v;
    x.f[0] = fmaxf(x.f[0], 0.f);
    x.f[1] = fmaxf(x.f[1], 0.f);
    return x.u;
}
// un-hoistable smem load: volatile keeps it inside the chunk loop so weights
// are NOT promoted to registers (the reg=255 / occ=12% failure mode).
__device__ __forceinline__ u64 lds64(const u64* p) {
    u64 v;
    unsigned a = (unsigned)__cvta_generic_to_shared(p);
    asm volatile("ld.shared.b64 %0, [%1];" : "=l"(v) : "r"(a));
    return v;
}

// ---------- single fused kernel: MLP + upsample + sigmoid + dice + finalize ----------
__global__ void __launch_bounds__(TB, 5) mask_kernel(
    const float* __restrict__ mf,
    const float* __restrict__ params,
    const float* __restrict__ iloc,
    const float* __restrict__ gt,
    const int*   __restrict__ im_inds,
    const int*   __restrict__ fpn,
    float*       __restrict__ out)
{
    const int b   = blockIdx.x;   // band 0..7 (17 input rows each)
    const int n   = blockIdx.y;   // instance
    const int tid = threadIdx.x;

    __shared__ __align__(16) u64 swp[NPAR];        // duplicated weight packs
    __shared__ __align__(16) u64 srx[WWW / 2];     // packed relx per pixel-pair
    __shared__ __align__(16) u64 sry[18];          // packed rely per band row
    __shared__ float sl[18 * WWW];                 // band logits
    __shared__ float red[3][TB / 32];

    const int   im   = __ldg(&im_inds[n]);
    const float sinv = 1.f / c_soi[__ldg(&fpn[n])];
    const float locx = __ldg(&iloc[2 * n]);
    const float locy = __ldg(&iloc[2 * n + 1]);

    const int r0    = b * 17;
    const int nrows = min(18, HH - r0);            // 18, last band 17

    for (int i = tid; i < NPAR; i += TB) {
        F2 t; t.f[0] = t.f[1] = params[n * NPAR + i];
        swp[i] = t.u;
    }
    for (int xp = tid; xp < WWW / 2; xp += TB) {
        int x = 2 * xp;
        srx[xp] = pk((locx - (float)(8 * x + 4))  * sinv,
                     (locx - (float)(8 * x + 12)) * sinv);
    }
    for (int r = tid; r < nrows; r += TB) {
        float ry = (locy - (float)(8 * (r0 + r) + 4)) * sinv;
        sry[r] = pk(ry, ry);
    }
    __syncthreads();

#define WLD(i) lds64(&swp[i])

    const int nchunks = nrows * 50;                // 4-px chunks per band
    const float* fimg = mf + (size_t)im * 8 * HW;

    // ---- phase 1: logits (4 px = 2 f32x2 packs per chunk) ----
    for (int g = tid; g < nchunks; g += TB) {
        const int row = g / 50;
        const int cx  = g - row * 50;
        const int xb  = cx * 4;
        const float* fb = fimg + (r0 + row) * WWW + xb;

        // layer 1: bias + rel coords
        u64 acc[8][2];
        {
            u64 xr0 = srx[cx * 2], xr1 = srx[cx * 2 + 1];
            u64 yr  = sry[row];
#pragma unroll
            for (int o = 0; o < 8; o++) {
                u64 bb = WLD(152 + o);
                u64 w0 = WLD(o * 10);
                u64 w1 = WLD(o * 10 + 1);
                acc[o][0] = fma2(w1, yr, fma2(w0, xr0, bb));
                acc[o][1] = fma2(w1, yr, fma2(w0, xr1, bb));
            }
        }
        // feat channels
#pragma unroll
        for (int c = 0; c < 8; c++) {
            float4 v = *(const float4*)(fb + (size_t)c * HW);  // 16B-aligned (xb%4==0)
            u64 x0 = pk(v.x, v.y), x1 = pk(v.z, v.w);
#pragma unroll
            for (int o = 0; o < 8; o++) {
                u64 w = WLD(o * 10 + 2 + c);
                acc[o][0] = fma2(w, x0, acc[o][0]);
                acc[o][1] = fma2(w, x1, acc[o][1]);
            }
        }
        u64 h[8][2];
#pragma unroll
        for (int o = 0; o < 8; o++) {
            h[o][0] = relu2(acc[o][0]);
            h[o][1] = relu2(acc[o][1]);
        }

        // layer 2 (reuse acc)
#pragma unroll
        for (int o = 0; o < 8; o++) {
            u64 bb = WLD(160 + o);
            acc[o][0] = bb; acc[o][1] = bb;
        }
#pragma unroll
        for (int c = 0; c < 8; c++) {
#pragma unroll
            for (int o = 0; o < 8; o++) {
                u64 w = WLD(80 + o * 8 + c);
                acc[o][0] = fma2(w, h[c][0], acc[o][0]);
                acc[o][1] = fma2(w, h[c][1], acc[o][1]);
            }
        }

        // layer 3
        u64 ov0 = WLD(168), ov1 = ov0;
#pragma unroll
        for (int c = 0; c < 8; c++) {
            u64 w = WLD(144 + c);
            ov0 = fma2(w, relu2(acc[c][0]), ov0);
            ov1 = fma2(w, relu2(acc[c][1]), ov1);
        }
        u64* slp = (u64*)&sl[row * WWW + xb];      // 8B-aligned
        slp[0] = ov0; slp[1] = ov1;
    }
    __syncthreads();

    // ---- phase 2: upsample + sigmoid + dice partials ----
    const int i_start = (r0 * 271 + 134) / 135;
    const int i_end   = (b == 7) ? OH : ((r0 + 17) * 271 + 134) / 135;
    const float* gtb  = gt + (size_t)n * OH * OW;

    float aI = 0.f, aS = 0.f, aT = 0.f;
    for (int i = i_start; i < i_end; i++) {
        const float fy = (float)i * (135.f / 271.f);
        const int   y0 = (int)fy;
        const float wy = fy - (float)y0;
        int ly0 = y0 - r0;
        int ly1 = min(y0 + 1, 135) - r0;
        ly0 = max(0, min(ly0, nrows - 1));
        ly1 = max(0, min(ly1, nrows - 1));
        const float* sl0 = &sl[ly0 * WWW];
        const float* sl1 = &sl[ly1 * WWW];
        const float* gtr = gtb + (size_t)i * OW;

        for (int j = tid; j < OW; j += TB) {
            float fx = (float)j * (199.f / 399.f);
            int   x0 = (int)fx;
            float wx = fx - (float)x0;
            int   x1 = min(x0 + 1, 199);

            float t00 = sl0[x0], t01 = sl0[x1];
            float t10 = sl1[x0], t11 = sl1[x1];
            float top = t00 + (t01 - t00) * wx;
            float bot = t10 + (t11 - t10) * wx;
            float v   = top + (bot - top) * wy;

            float s = __fdividef(1.f, 1.f + __expf(-v));
            float t = __ldg(&gtr[j]);

            aI = fmaf(s, t, aI);
            aS = fmaf(s, s, aS);
            aT += t;                               // t in {0,1}
        }
    }

#pragma unroll
    for (int off = 16; off > 0; off >>= 1) {
        aI += __shfl_down_sync(0xffffffffu, aI, off);
        aS += __shfl_down_sync(0xffffffffu, aS, off);
        aT += __shfl_down_sync(0xffffffffu, aT, off);
    }
    const int wid = tid >> 5, lane = tid & 31;
    if (lane == 0) { red[0][wid] = aI; red[1][wid] = aS; red[2][wid] = aT; }
    __syncthreads();

    // ---- phase 3: last band-block per instance finalizes the loss ----
    if (tid == 0) {
        float I = red[0][0] + red[0][1] + red[0][2] + red[0][3];
        float S = red[1][0] + red[1][1] + red[1][2] + red[1][3];
        float T = red[2][0] + red[2][1] + red[2][2] + red[2][3];
        float* gp = &g_part[(n * 8 + b) * 3];
        gp[0] = I; gp[1] = S; gp[2] = T;
        __threadfence();
        int old = atomicAdd(&g_count[n], 1);
        if (old == 7) {                 // last band of this instance
            __threadfence();
            float sI = 0.f, sS = 0.f, sT = 0.f;
#pragma unroll
            for (int k = 0; k < 8; k++) {
                const float* q = &g_part[(n * 8 + k) * 3];
                sI += q[0]; sS += q[1]; sT += q[2];
            }
            out[n] = 1.f - 2.f * sI / (sS + sT + 1e-5f);
            g_count[n] = 0;             // reset for next graph replay
        }
    }
}

extern "C" void kernel_launch(void* const* d_in, const int* in_sizes, int n_in,
                              void* d_out, int out_size) {
    const float* mf     = (const float*)d_in[0];
    const float* params = (const float*)d_in[1];
    const float* iloc   = (const float*)d_in[2];
    const float* gt     = (const float*)d_in[3];
    const int*   imi    = (const int*)d_in[4];
    const int*   fpn    = (const int*)d_in[5];
    float*       out    = (float*)d_out;

    dim3 grid(8, NINST);
    mask_kernel<<<grid, TB>>>(mf, params, iloc, gt, imi, fpn, out);
}

// round 11
// speedup vs baseline: 6.1885x; 1.9813x over previous
#include <cuda_runtime.h>

#define HH    136
#define WWW   200
#define HW    (HH*WWW)
#define OH    272
#define OW    400
#define NIMG  8
#define NINST 512
#define NPAR  169
#define TB    128

typedef unsigned long long u64;

__device__ float g_part[NINST * 8 * 3];   // per-(inst,band) partials
__device__ int   g_count[NINST];          // zero-init; finisher resets -> graph-safe

__constant__ float c_soi[6] = {64.f, 128.f, 256.f, 512.f, 1024.f, 2048.f};

// ---------- packed f32x2 helpers ----------
__device__ __forceinline__ u64 pk(float lo, float hi) {
    u64 r; asm("mov.b64 %0, {%1,%2};" : "=l"(r) : "f"(lo), "f"(hi)); return r;
}
__device__ __forceinline__ u64 fma2(u64 a, u64 b, u64 c) {
    u64 d; asm("fma.rn.f32x2 %0, %1, %2, %3;" : "=l"(d) : "l"(a), "l"(b), "l"(c)); return d;
}
union F2 { u64 u; float f[2]; };
__device__ __forceinline__ u64 relu2(u64 v) {
    F2 x; x.u = v;
    x.f[0] = fmaxf(x.f[0], 0.f);
    x.f[1] = fmaxf(x.f[1], 0.f);
    return x.u;
}
// un-hoistable smem load: volatile keeps weights OUT of registers
// (prevents the reg=255 / occ=12% loop-invariant hoisting failure mode).
__device__ __forceinline__ u64 lds64(const u64* p) {
    u64 v;
    unsigned a = (unsigned)__cvta_generic_to_shared(p);
    asm volatile("ld.shared.b64 %0, [%1];" : "=l"(v) : "r"(a));
    return v;
}

// ---------- single fused kernel: MLP + upsample + sigmoid + dice + finalize ----------
__global__ void __launch_bounds__(TB, 5) mask_kernel(
    const float* __restrict__ mf,
    const float* __restrict__ params,
    const float* __restrict__ iloc,
    const float* __restrict__ gt,
    const int*   __restrict__ im_inds,
    const int*   __restrict__ fpn,
    float*       __restrict__ out)
{
    const int b   = blockIdx.x;   // band 0..7 (17 input rows each)
    const int n   = blockIdx.y;   // instance
    const int tid = threadIdx.x;

    __shared__ __align__(16) u64 swp[NPAR];        // duplicated weight packs
    __shared__ __align__(16) u64 srx[WWW / 2];     // packed relx per pixel-pair
    __shared__ __align__(16) u64 sry[18];          // packed rely per band row
    __shared__ float sl[18 * WWW];                 // band logits
    __shared__ int   tx0[OW];                      // upsample x index table
    __shared__ float twx[OW];                      // upsample x weight table
    __shared__ float red[3][TB / 32];

    const int   im   = __ldg(&im_inds[n]);
    const float sinv = 1.f / c_soi[__ldg(&fpn[n])];
    const float locx = __ldg(&iloc[2 * n]);
    const float locy = __ldg(&iloc[2 * n + 1]);

    const int r0    = b * 17;
    const int nrows = min(18, HH - r0);            // 18, last band 17

    for (int i = tid; i < NPAR; i += TB) {
        F2 t; t.f[0] = t.f[1] = params[n * NPAR + i];
        swp[i] = t.u;
    }
    for (int xp = tid; xp < WWW / 2; xp += TB) {
        int x = 2 * xp;
        srx[xp] = pk((locx - (float)(8 * x + 4))  * sinv,
                     (locx - (float)(8 * x + 12)) * sinv);
    }
    for (int r = tid; r < nrows; r += TB) {
        float ry = (locy - (float)(8 * (r0 + r) + 4)) * sinv;
        sry[r] = pk(ry, ry);
    }
    for (int j = tid; j < OW; j += TB) {
        float fx = (float)j * (199.f / 399.f);
        int x0 = (int)fx;
        tx0[j] = x0;
        twx[j] = fx - (float)x0;
    }
    __syncthreads();

#define WLD(i) lds64(&swp[i])

    const int nchunks = nrows * 50;                // 4-px chunks per band
    const float* fimg = mf + (size_t)im * 8 * HW;

    // ---- phase 1: logits (4 px = 2 f32x2 packs; rolling feat prefetch) ----
    for (int g = tid; g < nchunks; g += TB) {
        const int row = g / 50;
        const int cx  = g - row * 50;
        const int xb  = cx * 4;
        const float* fb = fimg + (r0 + row) * WWW + xb;

        // layer 1: bias + rel coords
        u64 acc[8][2];
        {
            u64 xr0 = srx[cx * 2], xr1 = srx[cx * 2 + 1];
            u64 yr  = sry[row];
#pragma unroll
            for (int o = 0; o < 8; o++) {
                u64 bb = WLD(152 + o);
                u64 w0 = WLD(o * 10);
                u64 w1 = WLD(o * 10 + 1);
                acc[o][0] = fma2(w1, yr, fma2(w0, xr0, bb));
                acc[o][1] = fma2(w1, yr, fma2(w0, xr1, bb));
            }
        }
        // feat channels with depth-1 rolling prefetch
        float4 fc = *(const float4*)(fb);          // channel 0
#pragma unroll
        for (int c = 0; c < 8; c++) {
            float4 fn;
            if (c < 7) fn = *(const float4*)(fb + (size_t)(c + 1) * HW);
            u64 x0 = pk(fc.x, fc.y), x1 = pk(fc.z, fc.w);
#pragma unroll
            for (int o = 0; o < 8; o++) {
                u64 w = WLD(o * 10 + 2 + c);
                acc[o][0] = fma2(w, x0, acc[o][0]);
                acc[o][1] = fma2(w, x1, acc[o][1]);
            }
            fc = fn;
        }
        u64 h[8][2];
#pragma unroll
        for (int o = 0; o < 8; o++) {
            h[o][0] = relu2(acc[o][0]);
            h[o][1] = relu2(acc[o][1]);
        }

        // layer 2 (reuse acc)
#pragma unroll
        for (int o = 0; o < 8; o++) {
            u64 bb = WLD(160 + o);
            acc[o][0] = bb; acc[o][1] = bb;
        }
#pragma unroll
        for (int c = 0; c < 8; c++) {
#pragma unroll
            for (int o = 0; o < 8; o++) {
                u64 w = WLD(80 + o * 8 + c);
                acc[o][0] = fma2(w, h[c][0], acc[o][0]);
                acc[o][1] = fma2(w, h[c][1], acc[o][1]);
            }
        }

        // layer 3
        u64 ov0 = WLD(168), ov1 = ov0;
#pragma unroll
        for (int c = 0; c < 8; c++) {
            u64 w = WLD(144 + c);
            ov0 = fma2(w, relu2(acc[c][0]), ov0);
            ov1 = fma2(w, relu2(acc[c][1]), ov1);
        }
        u64* slp = (u64*)&sl[row * WWW + xb];      // 8B-aligned
        slp[0] = ov0; slp[1] = ov1;
    }
    __syncthreads();

    // ---- phase 2: upsample + sigmoid + dice (4 px / thread, float4 gt) ----
    const int i_start = (r0 * 271 + 134) / 135;
    const int i_end   = (b == 7) ? OH : ((r0 + 17) * 271 + 134) / 135;
    const float* gtb  = gt + (size_t)n * OH * OW;

    const int ngroups = (i_end - i_start) * (OW / 4);
    float aI = 0.f, aS = 0.f, aT = 0.f;
    for (int idx = tid; idx < ngroups; idx += TB) {
        const int ir = idx / (OW / 4);
        const int jg = (idx - ir * (OW / 4)) * 4;
        const int i  = i_start + ir;

        const float fy = (float)i * (135.f / 271.f);
        const int   y0 = (int)fy;
        const float wy = fy - (float)y0;
        int ly0 = y0 - r0;
        int ly1 = min(y0 + 1, 135) - r0;
        ly0 = max(0, min(ly0, nrows - 1));
        ly1 = max(0, min(ly1, nrows - 1));
        const float* sl0 = &sl[ly0 * WWW];
        const float* sl1 = &sl[ly1 * WWW];

        const float4 tq = *(const float4*)(gtb + (size_t)i * OW + jg);

#pragma unroll
        for (int k = 0; k < 4; k++) {
            const int j = jg + k;
            int   x0 = tx0[j];
            float wx = twx[j];
            int   x1 = min(x0 + 1, 199);

            float t00 = sl0[x0], t01 = sl0[x1];
            float t10 = sl1[x0], t11 = sl1[x1];
            float top = t00 + (t01 - t00) * wx;
            float bot = t10 + (t11 - t10) * wx;
            float v   = top + (bot - top) * wy;

            float s = __fdividef(1.f, 1.f + __expf(-v));
            float t = (&tq.x)[k];

            aI = fmaf(s, t, aI);
            aS = fmaf(s, s, aS);
            aT += t;                               // t in {0,1}
        }
    }

#pragma unroll
    for (int off = 16; off > 0; off >>= 1) {
        aI += __shfl_down_sync(0xffffffffu, aI, off);
        aS += __shfl_down_sync(0xffffffffu, aS, off);
        aT += __shfl_down_sync(0xffffffffu, aT, off);
    }
    const int wid = tid >> 5, lane = tid & 31;
    if (lane == 0) { red[0][wid] = aI; red[1][wid] = aS; red[2][wid] = aT; }
    __syncthreads();

    // ---- phase 3: last band-block per instance finalizes the loss ----
    if (tid == 0) {
        float I = red[0][0] + red[0][1] + red[0][2] + red[0][3];
        float S = red[1][0] + red[1][1] + red[1][2] + red[1][3];
        float T = red[2][0] + red[2][1] + red[2][2] + red[2][3];
        float* gp = &g_part[(n * 8 + b) * 3];
        gp[0] = I; gp[1] = S; gp[2] = T;
        __threadfence();
        int old = atomicAdd(&g_count[n], 1);
        if (old == 7) {                 // last band of this instance
            __threadfence();
            float sI = 0.f, sS = 0.f, sT = 0.f;
#pragma unroll
            for (int k = 0; k < 8; k++) {
                const float* q = &g_part[(n * 8 + k) * 3];
                sI += q[0]; sS += q[1]; sT += q[2];
            }
            out[n] = 1.f - 2.f * sI / (sS + sT + 1e-5f);
            g_count[n] = 0;             // reset for next graph replay
        }
    }
}

extern "C" void kernel_launch(void* const* d_in, const int* in_sizes, int n_in,
                              void* d_out, int out_size) {
    const float* mf     = (const float*)d_in[0];
    const float* params = (const float*)d_in[1];
    const float* iloc   = (const float*)d_in[2];
    const float* gt     = (const float*)d_in[3];
    const int*   imi    = (const int*)d_in[4];
    const int*   fpn    = (const int*)d_in[5];
    float*       out    = (float*)d_out;

    dim3 grid(8, NINST);
    mask_kernel<<<grid, TB>>>(mf, params, iloc, gt, imi, fpn, out);
}